// round 5
// baseline (speedup 1.0000x reference)
#include <cuda_runtime.h>

#define THREADS 256
#define NP 50          // padded token count (49 + 1 pad)

// ---------------- smem layout (floats) ----------------
// xs   [96][50]   @ 0       (4800)
// qkv  [288][50]  @ 4800    (14400)   rows 0..95 reused for attention output
// S    [49][50]   @ 19200   (2450)
// Pt   [49][50]   @ 21650   (2450)
// sinv [50]       @ 24100
// mu   [49]       @ 24150
// rs   [49]       @ 24199
// cnt  int[49]    @ 24248
#define SMEM_FLOATS 24297
#define SMEM_BYTES  (SMEM_FLOATS * 4)

__device__ float g_wT[96 * 288];   // qkv_w transposed: wT[c][m]
__device__ float g_pT[96 * 96];    // proj_w transposed: pT[c][m]

__device__ __forceinline__ float2 ffma2(float2 a, float2 b, float2 c) {
    float2 d;
    asm("fma.rn.f32x2 %0, %1, %2, %3;"
        : "=l"(reinterpret_cast<unsigned long long&>(d))
        : "l"(reinterpret_cast<unsigned long long&>(a)),
          "l"(reinterpret_cast<unsigned long long&>(b)),
          "l"(reinterpret_cast<unsigned long long&>(c)));
    return d;
}

__global__ void transpose_weights(const float* __restrict__ qkv_w,
                                  const float* __restrict__ proj_w) {
    int t = blockIdx.x * blockDim.x + threadIdx.x;
    if (t < 288 * 96) { int m = t / 96, c = t - m * 96; g_wT[c * 288 + m] = qkv_w[t]; }
    if (t < 96 * 96)  { int m = t / 96, c = t - m * 96; g_pT[c * 96 + m]  = proj_w[t]; }
}

__global__ __launch_bounds__(THREADS, 2)
void swin_fused(const float* __restrict__ x,
                const float* __restrict__ ln_g,
                const float* __restrict__ ln_b,
                const float* __restrict__ qkv_b,
                const float* __restrict__ proj_b,
                const float* __restrict__ rel_table,
                float* __restrict__ out) {
    extern __shared__ float sm[];
    float* xs   = sm;
    float* qkv  = sm + 4800;
    float* S    = sm + 19200;
    float* Pt   = sm + 21650;
    float* sinv = sm + 24100;
    float* mu   = sm + 24150;
    float* rs   = sm + 24199;
    int*   cnt  = (int*)(sm + 24248);

    const int tid = threadIdx.x;
    const int win = blockIdx.x;
    const int b   = win >> 6;
    const int wh  = (win >> 3) & 7;
    const int ww  = win & 7;

    // ---------------- phase 0: gather window (with cyclic shift) ----------------
    if (tid == 0) sinv[49] = 0.0f;
    if (tid < 49) {
        int yi = tid / 7, xi = tid - yi * 7;
        int hs = wh * 7 + yi, wsx = ww * 7 + xi;   // shifted-frame coords
        int rh = hs  < 49 ? 0 : (hs  < 53 ? 1 : 2);
        int rw = wsx < 49 ? 0 : (wsx < 53 ? 1 : 2);
        cnt[tid] = rh * 3 + rw;
    }
    const float* xb = x + (size_t)b * (96 * 3136);
    for (int e = tid; e < 96 * 49; e += THREADS) {
        int c = e / 49, i = e - c * 49;
        int yi = i / 7, xi = i - yi * 7;
        int h = wh * 7 + yi + 3; if (h >= 56) h -= 56;
        int w = ww * 7 + xi + 3; if (w >= 56) w -= 56;
        xs[c * NP + i] = __ldg(xb + c * 3136 + h * 56 + w);
    }
    __syncthreads();

    // ---------------- LayerNorm stats ----------------
    if (tid < 49) {
        float s = 0.f, q = 0.f;
        #pragma unroll 8
        for (int c = 0; c < 96; c++) { float v = xs[c * NP + tid]; s += v; q += v * v; }
        float m   = s * (1.f / 96.f);
        float var = fmaf(-m, m, q * (1.f / 96.f));
        mu[tid] = m;
        rs[tid] = rsqrtf(var + 1e-5f);
    }
    __syncthreads();

    for (int e = tid; e < 96 * 49; e += THREADS) {
        int c = e / 49, i = e - c * 49;
        float v = xs[c * NP + i];
        xs[c * NP + i] = (v - mu[i]) * rs[i] * __ldg(ln_g + c) + __ldg(ln_b + c);
    }
    if (tid < 96) xs[tid * NP + 49] = 0.0f;   // pad token
    __syncthreads();

    // ---------------- QKV GEMM: qkv[m][i] = xs[:, i] . wT[:, m] + b ----------------
    for (int task = tid; task < 36 * 49; task += THREADS) {
        int oct = task / 49;
        int i   = task - oct * 49;
        int m0  = oct * 8;
        float2 acc0 = make_float2(__ldg(qkv_b + m0 + 0), __ldg(qkv_b + m0 + 1));
        float2 acc1 = make_float2(__ldg(qkv_b + m0 + 2), __ldg(qkv_b + m0 + 3));
        float2 acc2 = make_float2(__ldg(qkv_b + m0 + 4), __ldg(qkv_b + m0 + 5));
        float2 acc3 = make_float2(__ldg(qkv_b + m0 + 6), __ldg(qkv_b + m0 + 7));
        const float* wp = g_wT + m0;
        const float* xp = xs + i;
        #pragma unroll 4
        for (int c = 0; c < 96; c++) {
            float4 wa = __ldg((const float4*)wp);
            float4 wb = __ldg((const float4*)(wp + 4));
            float  xv = *xp;
            float2 x2 = make_float2(xv, xv);
            acc0 = ffma2(make_float2(wa.x, wa.y), x2, acc0);
            acc1 = ffma2(make_float2(wa.z, wa.w), x2, acc1);
            acc2 = ffma2(make_float2(wb.x, wb.y), x2, acc2);
            acc3 = ffma2(make_float2(wb.z, wb.w), x2, acc3);
            wp += 288; xp += NP;
        }
        float* qr = qkv + m0 * NP + i;
        qr[0 * NP] = acc0.x; qr[1 * NP] = acc0.y;
        qr[2 * NP] = acc1.x; qr[3 * NP] = acc1.y;
        qr[4 * NP] = acc2.x; qr[5 * NP] = acc2.y;
        qr[6 * NP] = acc3.x; qr[7 * NP] = acc3.y;
    }
    __syncthreads();

    // ---------------- per-head attention ----------------
    const float scale = 0.1767766952966369f;   // 1/sqrt(32)
    for (int h = 0; h < 3; h++) {
        const float* qb = qkv + (h * 32) * NP;
        const float* kb = qkv + (96 + h * 32) * NP;
        const float* vb = qkv + (192 + h * 32) * NP;

        // S[i][j] = scale * q.k + bias + mask   (5 j-pairs per task)
        if (tid < 245) {
            int i  = tid / 5;
            int jg = tid - i * 5;
            float2 a0 = make_float2(0.f, 0.f), a1 = a0, a2 = a0, a3 = a0, a4 = a0;
            const float* qp = qb + i;
            const float* kp = kb + jg * 10;
            #pragma unroll 8
            for (int d = 0; d < 32; d++) {
                float  qv = *qp;
                float2 q2 = make_float2(qv, qv);
                const float2* kr = (const float2*)kp;
                a0 = ffma2(q2, kr[0], a0);
                a1 = ffma2(q2, kr[1], a1);
                a2 = ffma2(q2, kr[2], a2);
                a3 = ffma2(q2, kr[3], a3);
                a4 = ffma2(q2, kr[4], a4);
                qp += NP; kp += NP;
            }
            int yi = i / 7, xi = i - yi * 7;
            int ci = cnt[i];
            float vals[10] = {a0.x, a0.y, a1.x, a1.y, a2.x, a2.y, a3.x, a3.y, a4.x, a4.y};
            #pragma unroll
            for (int u = 0; u < 10; u++) {
                int j = jg * 10 + u;
                if (j < 49) {
                    int yj = j / 7, xj = j - yj * 7;
                    int idx = (yi - yj + 6) * 13 + (xi - xj + 6);
                    float bias = __ldg(rel_table + idx * 3 + h);
                    float msk  = (cnt[j] == ci) ? 0.f : -100.f;
                    S[i * NP + j] = fmaf(vals[u], scale, bias) + msk;
                }
            }
        }
        __syncthreads();

        // softmax per row, 4 threads/row; write transposed probs Pt[j][i]
        if (tid < 196) {
            int i  = tid >> 2;
            int q4 = tid & 3;
            int j0 = (q4 == 0) ? 0 : (13 + (q4 - 1) * 12);
            int j1 = j0 + ((q4 == 0) ? 13 : 12);
            unsigned msk32 = (tid < 192) ? 0xffffffffu : 0x0000000fu;
            const float* Srow = S + i * NP;
            float mx = -1e30f;
            for (int j = j0; j < j1; j++) mx = fmaxf(mx, Srow[j]);
            mx = fmaxf(mx, __shfl_xor_sync(msk32, mx, 1));
            mx = fmaxf(mx, __shfl_xor_sync(msk32, mx, 2));
            float sum = 0.f;
            for (int j = j0; j < j1; j++) {
                float e = __expf(Srow[j] - mx);
                Pt[j * NP + i] = e;
                sum += e;
            }
            sum += __shfl_xor_sync(msk32, sum, 1);
            sum += __shfl_xor_sync(msk32, sum, 2);
            if (q4 == 0) sinv[i] = 1.f / sum;
        }
        __syncthreads();

        // out[d][i] = (sum_j Pt[j][i] * v[d][j]) * sinv[i], overwrite q rows of head h
        if (tid < 160) {
            int d  = tid / 5;
            int ig = tid - d * 5;
            float2 a0 = make_float2(0.f, 0.f), a1 = a0, a2 = a0, a3 = a0, a4 = a0;
            const float* vp = vb + d * NP;
            const float* pp = Pt + ig * 10;
            #pragma unroll 7
            for (int j = 0; j < 49; j++) {
                float  vv = vp[j];
                float2 v2 = make_float2(vv, vv);
                const float2* pr = (const float2*)(pp + j * NP);
                a0 = ffma2(v2, pr[0], a0);
                a1 = ffma2(v2, pr[1], a1);
                a2 = ffma2(v2, pr[2], a2);
                a3 = ffma2(v2, pr[3], a3);
                a4 = ffma2(v2, pr[4], a4);
            }
            float* orow = qkv + (h * 32 + d) * NP + ig * 10;
            int i0 = ig * 10;
            orow[0] = a0.x * sinv[i0 + 0]; orow[1] = a0.y * sinv[i0 + 1];
            orow[2] = a1.x * sinv[i0 + 2]; orow[3] = a1.y * sinv[i0 + 3];
            orow[4] = a2.x * sinv[i0 + 4]; orow[5] = a2.y * sinv[i0 + 5];
            orow[6] = a3.x * sinv[i0 + 6]; orow[7] = a3.y * sinv[i0 + 7];
            orow[8] = a4.x * sinv[i0 + 8]; orow[9] = a4.y * sinv[i0 + 9];
        }
        __syncthreads();
    }

    // ---------------- proj GEMM + scatter store (inverse roll) ----------------
    for (int task = tid; task < 12 * 49; task += THREADS) {
        int oct = task / 49;
        int i   = task - oct * 49;
        int c0  = oct * 8;
        float2 acc0 = make_float2(__ldg(proj_b + c0 + 0), __ldg(proj_b + c0 + 1));
        float2 acc1 = make_float2(__ldg(proj_b + c0 + 2), __ldg(proj_b + c0 + 3));
        float2 acc2 = make_float2(__ldg(proj_b + c0 + 4), __ldg(proj_b + c0 + 5));
        float2 acc3 = make_float2(__ldg(proj_b + c0 + 6), __ldg(proj_b + c0 + 7));
        const float* wp = g_pT + c0;
        const float* xp = qkv + i;      // rows 0..95 hold merged attention output
        #pragma unroll 4
        for (int c = 0; c < 96; c++) {
            float4 wa = __ldg((const float4*)wp);
            float4 wb = __ldg((const float4*)(wp + 4));
            float  xv = *xp;
            float2 x2 = make_float2(xv, xv);
            acc0 = ffma2(make_float2(wa.x, wa.y), x2, acc0);
            acc1 = ffma2(make_float2(wa.z, wa.w), x2, acc1);
            acc2 = ffma2(make_float2(wb.x, wb.y), x2, acc2);
            acc3 = ffma2(make_float2(wb.z, wb.w), x2, acc3);
            wp += 96; xp += NP;
        }
        int yi = i / 7, xi = i - yi * 7;
        int h = wh * 7 + yi + 3; if (h >= 56) h -= 56;
        int w = ww * 7 + xi + 3; if (w >= 56) w -= 56;
        float* op = out + (size_t)(b * 96 + c0) * 3136 + h * 56 + w;
        op[0 * 3136] = acc0.x; op[1 * 3136] = acc0.y;
        op[2 * 3136] = acc1.x; op[3 * 3136] = acc1.y;
        op[4 * 3136] = acc2.x; op[5 * 3136] = acc2.y;
        op[6 * 3136] = acc3.x; op[7 * 3136] = acc3.y;
    }
}

extern "C" void kernel_launch(void* const* d_in, const int* in_sizes, int n_in,
                              void* d_out, int out_size) {
    const float* x         = (const float*)d_in[0];
    const float* ln_g      = (const float*)d_in[1];
    const float* ln_b      = (const float*)d_in[2];
    const float* qkv_w     = (const float*)d_in[3];
    const float* qkv_b     = (const float*)d_in[4];
    const float* proj_w    = (const float*)d_in[5];
    const float* proj_b    = (const float*)d_in[6];
    const float* rel_table = (const float*)d_in[7];
    float* out = (float*)d_out;

    cudaFuncSetAttribute(swin_fused, cudaFuncAttributeMaxDynamicSharedMemorySize, SMEM_BYTES);

    transpose_weights<<<108, 256>>>(qkv_w, proj_w);
    swin_fused<<<8192, THREADS, SMEM_BYTES>>>(x, ln_g, ln_b, qkv_b, proj_b, rel_table, out);
}

// round 6
// speedup vs baseline: 1.0024x; 1.0024x over previous
#include <cuda_runtime.h>

#define THREADS 256
#define NP 50          // padded token count (49 + 1 pad)

// ---------------- smem layout (floats) ----------------
// xs   [96][50]   @ 0       (4800)
// qkv  [288][50]  @ 4800    (14400)   rows 0..95 reused for attention output
// S    [49][50]   @ 19200   (2450)
// Pt   [49][50]   @ 21650   (2450)
// sinv [50]       @ 24100
// mu   [49]       @ 24150
// rs   [49]       @ 24199
// cnt  int[49]    @ 24248
#define SMEM_FLOATS 24297
#define SMEM_BYTES  (SMEM_FLOATS * 4)

__device__ float g_wT[96 * 288];   // qkv_w transposed: wT[c][m]
__device__ float g_pT[96 * 96];    // proj_w transposed: pT[c][m]

__device__ __forceinline__ float2 ffma2(float2 a, float2 b, float2 c) {
    float2 d;
    asm("fma.rn.f32x2 %0, %1, %2, %3;"
        : "=l"(reinterpret_cast<unsigned long long&>(d))
        : "l"(reinterpret_cast<unsigned long long&>(a)),
          "l"(reinterpret_cast<unsigned long long&>(b)),
          "l"(reinterpret_cast<unsigned long long&>(c)));
    return d;
}

__global__ void transpose_weights(const float* __restrict__ qkv_w,
                                  const float* __restrict__ proj_w) {
    int t = blockIdx.x * blockDim.x + threadIdx.x;
    if (t < 288 * 96) { int m = t / 96, c = t - m * 96; g_wT[c * 288 + m] = qkv_w[t]; }
    if (t < 96 * 96)  { int m = t / 96, c = t - m * 96; g_pT[c * 96 + m]  = proj_w[t]; }
}

__global__ __launch_bounds__(THREADS, 2)
void swin_fused(const float* __restrict__ x,
                const float* __restrict__ ln_g,
                const float* __restrict__ ln_b,
                const float* __restrict__ qkv_b,
                const float* __restrict__ proj_b,
                const float* __restrict__ rel_table,
                float* __restrict__ out) {
    extern __shared__ float sm[];
    float* xs   = sm;
    float* qkv  = sm + 4800;
    float* S    = sm + 19200;
    float* Pt   = sm + 21650;
    float* sinv = sm + 24100;
    float* mu   = sm + 24150;
    float* rs   = sm + 24199;
    int*   cnt  = (int*)(sm + 24248);

    const int tid = threadIdx.x;
    const int win = blockIdx.x;
    const int b   = win >> 6;
    const int wh  = (win >> 3) & 7;
    const int ww  = win & 7;

    // ---------------- phase 0: gather window (with cyclic shift) ----------------
    if (tid == 0) sinv[49] = 0.0f;
    if (tid < 49) {
        int yi = tid / 7, xi = tid - yi * 7;
        int hs = wh * 7 + yi, wsx = ww * 7 + xi;   // shifted-frame coords
        int rh = hs  < 49 ? 0 : (hs  < 53 ? 1 : 2);
        int rw = wsx < 49 ? 0 : (wsx < 53 ? 1 : 2);
        cnt[tid] = rh * 3 + rw;
    }
    const float* xb = x + (size_t)b * (96 * 3136);
    for (int e = tid; e < 96 * 49; e += THREADS) {
        int c = e / 49, i = e - c * 49;
        int yi = i / 7, xi = i - yi * 7;
        int h = wh * 7 + yi + 3; if (h >= 56) h -= 56;
        int w = ww * 7 + xi + 3; if (w >= 56) w -= 56;
        xs[c * NP + i] = __ldg(xb + c * 3136 + h * 56 + w);
    }
    __syncthreads();

    // ---------------- LayerNorm stats ----------------
    if (tid < 49) {
        float s = 0.f, q = 0.f;
        #pragma unroll 8
        for (int c = 0; c < 96; c++) { float v = xs[c * NP + tid]; s += v; q += v * v; }
        float m   = s * (1.f / 96.f);
        float var = fmaf(-m, m, q * (1.f / 96.f));
        mu[tid] = m;
        rs[tid] = rsqrtf(var + 1e-5f);
    }
    __syncthreads();

    for (int e = tid; e < 96 * 49; e += THREADS) {
        int c = e / 49, i = e - c * 49;
        float v = xs[c * NP + i];
        xs[c * NP + i] = (v - mu[i]) * rs[i] * __ldg(ln_g + c) + __ldg(ln_b + c);
    }
    if (tid < 96) xs[tid * NP + 49] = 0.0f;   // pad token
    __syncthreads();

    // ---------------- QKV GEMM: qkv[m][i] = xs[:, i] . wT[:, m] + b ----------------
    for (int task = tid; task < 36 * 49; task += THREADS) {
        int oct = task / 49;
        int i   = task - oct * 49;
        int m0  = oct * 8;
        float2 acc0 = make_float2(__ldg(qkv_b + m0 + 0), __ldg(qkv_b + m0 + 1));
        float2 acc1 = make_float2(__ldg(qkv_b + m0 + 2), __ldg(qkv_b + m0 + 3));
        float2 acc2 = make_float2(__ldg(qkv_b + m0 + 4), __ldg(qkv_b + m0 + 5));
        float2 acc3 = make_float2(__ldg(qkv_b + m0 + 6), __ldg(qkv_b + m0 + 7));
        const float* wp = g_wT + m0;
        const float* xp = xs + i;
        #pragma unroll 4
        for (int c = 0; c < 96; c++) {
            float4 wa = __ldg((const float4*)wp);
            float4 wb = __ldg((const float4*)(wp + 4));
            float  xv = *xp;
            float2 x2 = make_float2(xv, xv);
            acc0 = ffma2(make_float2(wa.x, wa.y), x2, acc0);
            acc1 = ffma2(make_float2(wa.z, wa.w), x2, acc1);
            acc2 = ffma2(make_float2(wb.x, wb.y), x2, acc2);
            acc3 = ffma2(make_float2(wb.z, wb.w), x2, acc3);
            wp += 288; xp += NP;
        }
        float* qr = qkv + m0 * NP + i;
        qr[0 * NP] = acc0.x; qr[1 * NP] = acc0.y;
        qr[2 * NP] = acc1.x; qr[3 * NP] = acc1.y;
        qr[4 * NP] = acc2.x; qr[5 * NP] = acc2.y;
        qr[6 * NP] = acc3.x; qr[7 * NP] = acc3.y;
    }
    __syncthreads();

    // ---------------- per-head attention ----------------
    const float scale = 0.1767766952966369f;   // 1/sqrt(32)
    for (int h = 0; h < 3; h++) {
        const float* qb = qkv + (h * 32) * NP;
        const float* kb = qkv + (96 + h * 32) * NP;
        const float* vb = qkv + (192 + h * 32) * NP;

        // S[i][j] = scale * q.k + bias + mask   (5 j-pairs per task)
        if (tid < 245) {
            int i  = tid / 5;
            int jg = tid - i * 5;
            float2 a0 = make_float2(0.f, 0.f), a1 = a0, a2 = a0, a3 = a0, a4 = a0;
            const float* qp = qb + i;
            const float* kp = kb + jg * 10;
            #pragma unroll 8
            for (int d = 0; d < 32; d++) {
                float  qv = *qp;
                float2 q2 = make_float2(qv, qv);
                const float2* kr = (const float2*)kp;
                a0 = ffma2(q2, kr[0], a0);
                a1 = ffma2(q2, kr[1], a1);
                a2 = ffma2(q2, kr[2], a2);
                a3 = ffma2(q2, kr[3], a3);
                a4 = ffma2(q2, kr[4], a4);
                qp += NP; kp += NP;
            }
            int yi = i / 7, xi = i - yi * 7;
            int ci = cnt[i];
            float vals[10] = {a0.x, a0.y, a1.x, a1.y, a2.x, a2.y, a3.x, a3.y, a4.x, a4.y};
            #pragma unroll
            for (int u = 0; u < 10; u++) {
                int j = jg * 10 + u;
                if (j < 49) {
                    int yj = j / 7, xj = j - yj * 7;
                    int idx = (yi - yj + 6) * 13 + (xi - xj + 6);
                    float bias = __ldg(rel_table + idx * 3 + h);
                    float msk  = (cnt[j] == ci) ? 0.f : -100.f;
                    S[i * NP + j] = fmaf(vals[u], scale, bias) + msk;
                }
            }
        }
        __syncthreads();

        // softmax per row, 4 threads/row; write transposed probs Pt[j][i]
        if (tid < 196) {
            int i  = tid >> 2;
            int q4 = tid & 3;
            int j0 = (q4 == 0) ? 0 : (13 + (q4 - 1) * 12);
            int j1 = j0 + ((q4 == 0) ? 13 : 12);
            unsigned msk32 = (tid < 192) ? 0xffffffffu : 0x0000000fu;
            const float* Srow = S + i * NP;
            float mx = -1e30f;
            for (int j = j0; j < j1; j++) mx = fmaxf(mx, Srow[j]);
            mx = fmaxf(mx, __shfl_xor_sync(msk32, mx, 1));
            mx = fmaxf(mx, __shfl_xor_sync(msk32, mx, 2));
            float sum = 0.f;
            for (int j = j0; j < j1; j++) {
                float e = __expf(Srow[j] - mx);
                Pt[j * NP + i] = e;
                sum += e;
            }
            sum += __shfl_xor_sync(msk32, sum, 1);
            sum += __shfl_xor_sync(msk32, sum, 2);
            if (q4 == 0) sinv[i] = 1.f / sum;
        }
        __syncthreads();

        // out[d][i] = (sum_j Pt[j][i] * v[d][j]) * sinv[i], overwrite q rows of head h
        if (tid < 160) {
            int d  = tid / 5;
            int ig = tid - d * 5;
            float2 a0 = make_float2(0.f, 0.f), a1 = a0, a2 = a0, a3 = a0, a4 = a0;
            const float* vp = vb + d * NP;
            const float* pp = Pt + ig * 10;
            #pragma unroll 7
            for (int j = 0; j < 49; j++) {
                float  vv = vp[j];
                float2 v2 = make_float2(vv, vv);
                const float2* pr = (const float2*)(pp + j * NP);
                a0 = ffma2(v2, pr[0], a0);
                a1 = ffma2(v2, pr[1], a1);
                a2 = ffma2(v2, pr[2], a2);
                a3 = ffma2(v2, pr[3], a3);
                a4 = ffma2(v2, pr[4], a4);
            }
            float* orow = qkv + (h * 32 + d) * NP + ig * 10;
            int i0 = ig * 10;
            orow[0] = a0.x * sinv[i0 + 0]; orow[1] = a0.y * sinv[i0 + 1];
            orow[2] = a1.x * sinv[i0 + 2]; orow[3] = a1.y * sinv[i0 + 3];
            orow[4] = a2.x * sinv[i0 + 4]; orow[5] = a2.y * sinv[i0 + 5];
            orow[6] = a3.x * sinv[i0 + 6]; orow[7] = a3.y * sinv[i0 + 7];
            orow[8] = a4.x * sinv[i0 + 8]; orow[9] = a4.y * sinv[i0 + 9];
        }
        __syncthreads();
    }

    // ---------------- proj GEMM + scatter store (inverse roll) ----------------
    for (int task = tid; task < 12 * 49; task += THREADS) {
        int oct = task / 49;
        int i   = task - oct * 49;
        int c0  = oct * 8;
        float2 acc0 = make_float2(__ldg(proj_b + c0 + 0), __ldg(proj_b + c0 + 1));
        float2 acc1 = make_float2(__ldg(proj_b + c0 + 2), __ldg(proj_b + c0 + 3));
        float2 acc2 = make_float2(__ldg(proj_b + c0 + 4), __ldg(proj_b + c0 + 5));
        float2 acc3 = make_float2(__ldg(proj_b + c0 + 6), __ldg(proj_b + c0 + 7));
        const float* wp = g_pT + c0;
        const float* xp = qkv + i;      // rows 0..95 hold merged attention output
        #pragma unroll 4
        for (int c = 0; c < 96; c++) {
            float4 wa = __ldg((const float4*)wp);
            float4 wb = __ldg((const float4*)(wp + 4));
            float  xv = *xp;
            float2 x2 = make_float2(xv, xv);
            acc0 = ffma2(make_float2(wa.x, wa.y), x2, acc0);
            acc1 = ffma2(make_float2(wa.z, wa.w), x2, acc1);
            acc2 = ffma2(make_float2(wb.x, wb.y), x2, acc2);
            acc3 = ffma2(make_float2(wb.z, wb.w), x2, acc3);
            wp += 96; xp += NP;
        }
        int yi = i / 7, xi = i - yi * 7;
        int h = wh * 7 + yi + 3; if (h >= 56) h -= 56;
        int w = ww * 7 + xi + 3; if (w >= 56) w -= 56;
        float* op = out + (size_t)(b * 96 + c0) * 3136 + h * 56 + w;
        op[0 * 3136] = acc0.x; op[1 * 3136] = acc0.y;
        op[2 * 3136] = acc1.x; op[3 * 3136] = acc1.y;
        op[4 * 3136] = acc2.x; op[5 * 3136] = acc2.y;
        op[6 * 3136] = acc3.x; op[7 * 3136] = acc3.y;
    }
}

extern "C" void kernel_launch(void* const* d_in, const int* in_sizes, int n_in,
                              void* d_out, int out_size) {
    const float* x         = (const float*)d_in[0];
    const float* ln_g      = (const float*)d_in[1];
    const float* ln_b      = (const float*)d_in[2];
    const float* qkv_w     = (const float*)d_in[3];
    const float* qkv_b     = (const float*)d_in[4];
    const float* proj_w    = (const float*)d_in[5];
    const float* proj_b    = (const float*)d_in[6];
    const float* rel_table = (const float*)d_in[7];
    float* out = (float*)d_out;

    cudaFuncSetAttribute(swin_fused, cudaFuncAttributeMaxDynamicSharedMemorySize, SMEM_BYTES);

    transpose_weights<<<108, 256>>>(qkv_w, proj_w);
    swin_fused<<<8192, THREADS, SMEM_BYTES>>>(x, ln_g, ln_b, qkv_b, proj_b, rel_table, out);
}

// round 7
// speedup vs baseline: 1.0047x; 1.0023x over previous
#include <cuda_runtime.h>

#define THREADS 256
#define NP 50          // padded token count (49 + 1 pad)

// ---------------- smem layout (floats) ----------------
// xs   [96][50]   @ 0       (4800)
// qkv  [288][50]  @ 4800    (14400)   rows 0..95 reused for attention output
// S    [49][50]   @ 19200   (2450)
// Pt   [49][50]   @ 21650   (2450)
// sinv [50]       @ 24100
// mu   [49]       @ 24150
// rs   [49]       @ 24199
// cnt  int[49]    @ 24248
#define SMEM_FLOATS 24297
#define SMEM_BYTES  (SMEM_FLOATS * 4)

__device__ float g_wT[96 * 288];   // qkv_w transposed: wT[c][m]
__device__ float g_pT[96 * 96];    // proj_w transposed: pT[c][m]

__device__ __forceinline__ float2 ffma2(float2 a, float2 b, float2 c) {
    float2 d;
    asm("fma.rn.f32x2 %0, %1, %2, %3;"
        : "=l"(reinterpret_cast<unsigned long long&>(d))
        : "l"(reinterpret_cast<unsigned long long&>(a)),
          "l"(reinterpret_cast<unsigned long long&>(b)),
          "l"(reinterpret_cast<unsigned long long&>(c)));
    return d;
}

__global__ void transpose_weights(const float* __restrict__ qkv_w,
                                  const float* __restrict__ proj_w) {
    int t = blockIdx.x * blockDim.x + threadIdx.x;
    if (t < 288 * 96) { int m = t / 96, c = t - m * 96; g_wT[c * 288 + m] = qkv_w[t]; }
    if (t < 96 * 96)  { int m = t / 96, c = t - m * 96; g_pT[c * 96 + m]  = proj_w[t]; }
}

__global__ __launch_bounds__(THREADS, 2)
void swin_fused(const float* __restrict__ x,
                const float* __restrict__ ln_g,
                const float* __restrict__ ln_b,
                const float* __restrict__ qkv_b,
                const float* __restrict__ proj_b,
                const float* __restrict__ rel_table,
                float* __restrict__ out) {
    extern __shared__ float sm[];
    float* xs   = sm;
    float* qkv  = sm + 4800;
    float* S    = sm + 19200;
    float* Pt   = sm + 21650;
    float* sinv = sm + 24100;
    float* mu   = sm + 24150;
    float* rs   = sm + 24199;
    int*   cnt  = (int*)(sm + 24248);

    const int tid = threadIdx.x;
    const int win = blockIdx.x;
    const int b   = win >> 6;
    const int wh  = (win >> 3) & 7;
    const int ww  = win & 7;

    // ---------------- phase 0: gather window (with cyclic shift) ----------------
    if (tid == 0) sinv[49] = 0.0f;
    if (tid < 49) {
        int yi = tid / 7, xi = tid - yi * 7;
        int hs = wh * 7 + yi, wsx = ww * 7 + xi;   // shifted-frame coords
        int rh = hs  < 49 ? 0 : (hs  < 53 ? 1 : 2);
        int rw = wsx < 49 ? 0 : (wsx < 53 ? 1 : 2);
        cnt[tid] = rh * 3 + rw;
    }
    const float* xb = x + (size_t)b * (96 * 3136);
    for (int e = tid; e < 96 * 49; e += THREADS) {
        int c = e / 49, i = e - c * 49;
        int yi = i / 7, xi = i - yi * 7;
        int h = wh * 7 + yi + 3; if (h >= 56) h -= 56;
        int w = ww * 7 + xi + 3; if (w >= 56) w -= 56;
        xs[c * NP + i] = __ldg(xb + c * 3136 + h * 56 + w);
    }
    __syncthreads();

    // ---------------- LayerNorm stats ----------------
    if (tid < 49) {
        float s = 0.f, q = 0.f;
        #pragma unroll 8
        for (int c = 0; c < 96; c++) { float v = xs[c * NP + tid]; s += v; q += v * v; }
        float m   = s * (1.f / 96.f);
        float var = fmaf(-m, m, q * (1.f / 96.f));
        mu[tid] = m;
        rs[tid] = rsqrtf(var + 1e-5f);
    }
    __syncthreads();

    for (int e = tid; e < 96 * 49; e += THREADS) {
        int c = e / 49, i = e - c * 49;
        float v = xs[c * NP + i];
        xs[c * NP + i] = (v - mu[i]) * rs[i] * __ldg(ln_g + c) + __ldg(ln_b + c);
    }
    if (tid < 96) xs[tid * NP + 49] = 0.0f;   // pad token
    __syncthreads();

    // ---------------- QKV GEMM: qkv[m][i] = xs[:, i] . wT[:, m] + b ----------------
    for (int task = tid; task < 36 * 49; task += THREADS) {
        int oct = task / 49;
        int i   = task - oct * 49;
        int m0  = oct * 8;
        float2 acc0 = make_float2(__ldg(qkv_b + m0 + 0), __ldg(qkv_b + m0 + 1));
        float2 acc1 = make_float2(__ldg(qkv_b + m0 + 2), __ldg(qkv_b + m0 + 3));
        float2 acc2 = make_float2(__ldg(qkv_b + m0 + 4), __ldg(qkv_b + m0 + 5));
        float2 acc3 = make_float2(__ldg(qkv_b + m0 + 6), __ldg(qkv_b + m0 + 7));
        const float* wp = g_wT + m0;
        const float* xp = xs + i;
        #pragma unroll 4
        for (int c = 0; c < 96; c++) {
            float4 wa = __ldg((const float4*)wp);
            float4 wb = __ldg((const float4*)(wp + 4));
            float  xv = *xp;
            float2 x2 = make_float2(xv, xv);
            acc0 = ffma2(make_float2(wa.x, wa.y), x2, acc0);
            acc1 = ffma2(make_float2(wa.z, wa.w), x2, acc1);
            acc2 = ffma2(make_float2(wb.x, wb.y), x2, acc2);
            acc3 = ffma2(make_float2(wb.z, wb.w), x2, acc3);
            wp += 288; xp += NP;
        }
        float* qr = qkv + m0 * NP + i;
        qr[0 * NP] = acc0.x; qr[1 * NP] = acc0.y;
        qr[2 * NP] = acc1.x; qr[3 * NP] = acc1.y;
        qr[4 * NP] = acc2.x; qr[5 * NP] = acc2.y;
        qr[6 * NP] = acc3.x; qr[7 * NP] = acc3.y;
    }
    __syncthreads();

    // ---------------- per-head attention ----------------
    const float scale = 0.1767766952966369f;   // 1/sqrt(32)
    for (int h = 0; h < 3; h++) {
        const float* qb = qkv + (h * 32) * NP;
        const float* kb = qkv + (96 + h * 32) * NP;
        const float* vb = qkv + (192 + h * 32) * NP;

        // S[i][j] = scale * q.k + bias + mask   (5 j-pairs per task)
        if (tid < 245) {
            int i  = tid / 5;
            int jg = tid - i * 5;
            float2 a0 = make_float2(0.f, 0.f), a1 = a0, a2 = a0, a3 = a0, a4 = a0;
            const float* qp = qb + i;
            const float* kp = kb + jg * 10;
            #pragma unroll 8
            for (int d = 0; d < 32; d++) {
                float  qv = *qp;
                float2 q2 = make_float2(qv, qv);
                const float2* kr = (const float2*)kp;
                a0 = ffma2(q2, kr[0], a0);
                a1 = ffma2(q2, kr[1], a1);
                a2 = ffma2(q2, kr[2], a2);
                a3 = ffma2(q2, kr[3], a3);
                a4 = ffma2(q2, kr[4], a4);
                qp += NP; kp += NP;
            }
            int yi = i / 7, xi = i - yi * 7;
            int ci = cnt[i];
            float vals[10] = {a0.x, a0.y, a1.x, a1.y, a2.x, a2.y, a3.x, a3.y, a4.x, a4.y};
            #pragma unroll
            for (int u = 0; u < 10; u++) {
                int j = jg * 10 + u;
                if (j < 49) {
                    int yj = j / 7, xj = j - yj * 7;
                    int idx = (yi - yj + 6) * 13 + (xi - xj + 6);
                    float bias = __ldg(rel_table + idx * 3 + h);
                    float msk  = (cnt[j] == ci) ? 0.f : -100.f;
                    S[i * NP + j] = fmaf(vals[u], scale, bias) + msk;
                }
            }
        }
        __syncthreads();

        // softmax per row, 4 threads/row; write transposed probs Pt[j][i]
        if (tid < 196) {
            int i  = tid >> 2;
            int q4 = tid & 3;
            int j0 = (q4 == 0) ? 0 : (13 + (q4 - 1) * 12);
            int j1 = j0 + ((q4 == 0) ? 13 : 12);
            unsigned msk32 = (tid < 192) ? 0xffffffffu : 0x0000000fu;
            const float* Srow = S + i * NP;
            float mx = -1e30f;
            for (int j = j0; j < j1; j++) mx = fmaxf(mx, Srow[j]);
            mx = fmaxf(mx, __shfl_xor_sync(msk32, mx, 1));
            mx = fmaxf(mx, __shfl_xor_sync(msk32, mx, 2));
            float sum = 0.f;
            for (int j = j0; j < j1; j++) {
                float e = __expf(Srow[j] - mx);
                Pt[j * NP + i] = e;
                sum += e;
            }
            sum += __shfl_xor_sync(msk32, sum, 1);
            sum += __shfl_xor_sync(msk32, sum, 2);
            if (q4 == 0) sinv[i] = 1.f / sum;
        }
        __syncthreads();

        // out[d][i] = (sum_j Pt[j][i] * v[d][j]) * sinv[i], overwrite q rows of head h
        if (tid < 160) {
            int d  = tid / 5;
            int ig = tid - d * 5;
            float2 a0 = make_float2(0.f, 0.f), a1 = a0, a2 = a0, a3 = a0, a4 = a0;
            const float* vp = vb + d * NP;
            const float* pp = Pt + ig * 10;
            #pragma unroll 7
            for (int j = 0; j < 49; j++) {
                float  vv = vp[j];
                float2 v2 = make_float2(vv, vv);
                const float2* pr = (const float2*)(pp + j * NP);
                a0 = ffma2(v2, pr[0], a0);
                a1 = ffma2(v2, pr[1], a1);
                a2 = ffma2(v2, pr[2], a2);
                a3 = ffma2(v2, pr[3], a3);
                a4 = ffma2(v2, pr[4], a4);
            }
            float* orow = qkv + (h * 32 + d) * NP + ig * 10;
            int i0 = ig * 10;
            orow[0] = a0.x * sinv[i0 + 0]; orow[1] = a0.y * sinv[i0 + 1];
            orow[2] = a1.x * sinv[i0 + 2]; orow[3] = a1.y * sinv[i0 + 3];
            orow[4] = a2.x * sinv[i0 + 4]; orow[5] = a2.y * sinv[i0 + 5];
            orow[6] = a3.x * sinv[i0 + 6]; orow[7] = a3.y * sinv[i0 + 7];
            orow[8] = a4.x * sinv[i0 + 8]; orow[9] = a4.y * sinv[i0 + 9];
        }
        __syncthreads();
    }

    // ---------------- proj GEMM + scatter store (inverse roll) ----------------
    for (int task = tid; task < 12 * 49; task += THREADS) {
        int oct = task / 49;
        int i   = task - oct * 49;
        int c0  = oct * 8;
        float2 acc0 = make_float2(__ldg(proj_b + c0 + 0), __ldg(proj_b + c0 + 1));
        float2 acc1 = make_float2(__ldg(proj_b + c0 + 2), __ldg(proj_b + c0 + 3));
        float2 acc2 = make_float2(__ldg(proj_b + c0 + 4), __ldg(proj_b + c0 + 5));
        float2 acc3 = make_float2(__ldg(proj_b + c0 + 6), __ldg(proj_b + c0 + 7));
        const float* wp = g_pT + c0;
        const float* xp = qkv + i;      // rows 0..95 hold merged attention output
        #pragma unroll 4
        for (int c = 0; c < 96; c++) {
            float4 wa = __ldg((const float4*)wp);
            float4 wb = __ldg((const float4*)(wp + 4));
            float  xv = *xp;
            float2 x2 = make_float2(xv, xv);
            acc0 = ffma2(make_float2(wa.x, wa.y), x2, acc0);
            acc1 = ffma2(make_float2(wa.z, wa.w), x2, acc1);
            acc2 = ffma2(make_float2(wb.x, wb.y), x2, acc2);
            acc3 = ffma2(make_float2(wb.z, wb.w), x2, acc3);
            wp += 96; xp += NP;
        }
        int yi = i / 7, xi = i - yi * 7;
        int h = wh * 7 + yi + 3; if (h >= 56) h -= 56;
        int w = ww * 7 + xi + 3; if (w >= 56) w -= 56;
        float* op = out + (size_t)(b * 96 + c0) * 3136 + h * 56 + w;
        op[0 * 3136] = acc0.x; op[1 * 3136] = acc0.y;
        op[2 * 3136] = acc1.x; op[3 * 3136] = acc1.y;
        op[4 * 3136] = acc2.x; op[5 * 3136] = acc2.y;
        op[6 * 3136] = acc3.x; op[7 * 3136] = acc3.y;
    }
}

extern "C" void kernel_launch(void* const* d_in, const int* in_sizes, int n_in,
                              void* d_out, int out_size) {
    const float* x         = (const float*)d_in[0];
    const float* ln_g      = (const float*)d_in[1];
    const float* ln_b      = (const float*)d_in[2];
    const float* qkv_w     = (const float*)d_in[3];
    const float* qkv_b     = (const float*)d_in[4];
    const float* proj_w    = (const float*)d_in[5];
    const float* proj_b    = (const float*)d_in[6];
    const float* rel_table = (const float*)d_in[7];
    float* out = (float*)d_out;

    cudaFuncSetAttribute(swin_fused, cudaFuncAttributeMaxDynamicSharedMemorySize, SMEM_BYTES);

    transpose_weights<<<108, 256>>>(qkv_w, proj_w);
    swin_fused<<<8192, THREADS, SMEM_BYTES>>>(x, ln_g, ln_b, qkv_b, proj_b, rel_table, out);
}